// round 1
// baseline (speedup 1.0000x reference)
#include <cuda_runtime.h>
#include <math.h>

#define BB 16
#define NN 8192
#define DD 512
#define HH 8
#define KSEED 4
#define OO 32            // KSEED*HH, o = i*8 + h
#define NCH3 32          // chunks per batch in K3
#define NPC3 256         // n per chunk in K3

// ---- scratch (no allocations allowed; __device__ globals) ----
__device__ float g_q[KSEED * DD];
__device__ float g_P[OO * DD];
__device__ float g_c0[OO];
__device__ float g_S[(size_t)BB * OO * NN];      // scores, then exp() in place
__device__ float g_invl[BB * OO];
__device__ float g_ypart[(size_t)BB * NCH3 * OO * DD];

// ---- packed f32x2 helpers ----
__device__ __forceinline__ unsigned long long pack2(float lo, float hi) {
    unsigned long long r;
    asm("mov.b64 %0, {%1,%2};" : "=l"(r)
        : "r"(__float_as_uint(lo)), "r"(__float_as_uint(hi)));
    return r;
}
__device__ __forceinline__ void unpack2(unsigned long long v, float& lo, float& hi) {
    unsigned a, b;
    asm("mov.b64 {%0,%1}, %2;" : "=r"(a), "=r"(b) : "l"(v));
    lo = __uint_as_float(a); hi = __uint_as_float(b);
}
__device__ __forceinline__ unsigned long long fma2(unsigned long long a,
                                                   unsigned long long b,
                                                   unsigned long long c) {
    unsigned long long d;
    asm("fma.rn.f32x2 %0, %1, %2, %3;" : "=l"(d) : "l"(a), "l"(b), "l"(c));
    return d;
}

// ---- K0a: q[i,c] = sum_e seed[i,e]*Wq[c,e] + bq[c] ----
__global__ void k0a_q(const float* __restrict__ seed,
                      const float* __restrict__ Wq,
                      const float* __restrict__ bq) {
    int i = blockIdx.x;      // 4 blocks
    int c = threadIdx.x;     // 512 threads
    const float4* w  = (const float4*)(Wq + (size_t)c * DD);
    const float4* sd = (const float4*)(seed + (size_t)i * DD);
    float acc = 0.f;
#pragma unroll 4
    for (int e4 = 0; e4 < DD / 4; e4++) {
        float4 a = w[e4], s4 = sd[e4];
        acc += a.x * s4.x + a.y * s4.y + a.z * s4.z + a.w * s4.w;
    }
    g_q[i * DD + c] = acc + bq[c];
}

// ---- K0b: P[(i*8+h),c] = (1/8) sum_d q[i,h*64+d] * Wk[h*64+d, c]; c0 likewise ----
__global__ void k0b_P(const float* __restrict__ Wk,
                      const float* __restrict__ bk) {
    __shared__ float qsh[KSEED * 64];
    int h = blockIdx.x;      // 8 blocks
    int c = threadIdx.x;     // 512 threads
    if (c < KSEED * 64) {
        int i = c >> 6, d = c & 63;
        qsh[c] = g_q[i * DD + h * 64 + d];
    }
    __syncthreads();
    float acc[KSEED] = {0.f, 0.f, 0.f, 0.f};
    for (int d = 0; d < 64; d++) {
        float w = Wk[(size_t)(h * 64 + d) * DD + c];
#pragma unroll
        for (int i = 0; i < KSEED; i++) acc[i] += qsh[i * 64 + d] * w;
    }
#pragma unroll
    for (int i = 0; i < KSEED; i++)
        g_P[(size_t)(i * HH + h) * DD + c] = acc[i] * 0.125f;
    if (c < KSEED) {
        float a = 0.f;
        for (int d = 0; d < 64; d++) a += qsh[c * 64 + d] * bk[h * 64 + d];
        g_c0[c * HH + h] = a * 0.125f;
    }
}

// ---- K1: scores s[b,o,n] = P[o]·X[b,n] + c0[o] ----
__global__ __launch_bounds__(256) void k1_scores(const float* __restrict__ X) {
    __shared__ float Psh[OO * DD];   // 64 KB
    __shared__ float c0sh[OO];
    int b = blockIdx.y;
    int nbase = blockIdx.x * 64;
    int t = threadIdx.x;             // 256
    for (int idx = t; idx < OO * DD / 4; idx += 256)
        ((float4*)Psh)[idx] = ((const float4*)g_P)[idx];
    if (t < OO) c0sh[t] = g_c0[t];
    __syncthreads();

    int qtr = t & 3;
    int n = nbase + (t >> 2);
    const float4* xp = (const float4*)(X + ((size_t)b * NN + n) * DD);

    unsigned long long acc[OO];
#pragma unroll
    for (int o = 0; o < OO; o++) acc[o] = 0ULL;

#pragma unroll 1
    for (int k = 0; k < 32; k++) {
        float4 x4 = xp[k * 4 + qtr];                     // c = k*16 + qtr*4 + j
        unsigned long long x01 = pack2(x4.x, x4.y);
        unsigned long long x23 = pack2(x4.z, x4.w);
        int cb = k * 16 + qtr * 4;
#pragma unroll
        for (int o = 0; o < OO; o++) {
            float4 p4 = *((const float4*)(Psh + o * DD + cb));
            acc[o] = fma2(pack2(p4.x, p4.y), x01, acc[o]);
            acc[o] = fma2(pack2(p4.z, p4.w), x23, acc[o]);
        }
    }
#pragma unroll
    for (int o = 0; o < OO; o++) {
        float lo, hi; unpack2(acc[o], lo, hi);
        float s = lo + hi;
        s += __shfl_xor_sync(0xffffffffu, s, 1);
        s += __shfl_xor_sync(0xffffffffu, s, 2);
        if (qtr == 0) g_S[((size_t)b * OO + o) * NN + n] = s + c0sh[o];
    }
}

// ---- K2: softmax stats per (b,o): s <- exp(s-m); invl = 1/sum ----
__global__ __launch_bounds__(256) void k2_softmax() {
    int bo = blockIdx.x;             // 512 blocks
    float* s = g_S + (size_t)bo * NN;
    int t = threadIdx.x;
    __shared__ float red[256];
    float m = -1e30f;
    for (int n = t; n < NN; n += 256) m = fmaxf(m, s[n]);
    red[t] = m; __syncthreads();
    for (int st = 128; st > 0; st >>= 1) {
        if (t < st) red[t] = fmaxf(red[t], red[t + st]);
        __syncthreads();
    }
    m = red[0]; __syncthreads();
    float sum = 0.f;
    for (int n = t; n < NN; n += 256) {
        float e = expf(s[n] - m);
        s[n] = e;
        sum += e;
    }
    red[t] = sum; __syncthreads();
    for (int st = 128; st > 0; st >>= 1) {
        if (t < st) red[t] += red[t + st];
        __syncthreads();
    }
    if (t == 0) g_invl[bo] = 1.0f / red[0];
}

// ---- K3: partial pooled sums y_part[b,ch,o,c] = sum_{n in ch} w[b,o,n] * X[b,n,c] ----
__global__ __launch_bounds__(256) void k3_accum(const float* __restrict__ X) {
    int b = blockIdx.y;
    int ch = blockIdx.x;
    int nbase = ch * NPC3;
    int t = threadIdx.x;             // 256 threads, c-pair = 2t
    __shared__ float wsh[8][OO];
    __shared__ float invl[OO];
    if (t < OO) invl[t] = g_invl[b * OO + t];
    __syncthreads();

    unsigned long long acc[OO];
#pragma unroll
    for (int o = 0; o < OO; o++) acc[o] = 0ULL;

    const float* Xb = X + (size_t)b * NN * DD;
    for (int nt = 0; nt < NPC3; nt += 8) {
        __syncthreads();
        {
            int o = t >> 3, ns = t & 7;
            wsh[ns][o] = g_S[((size_t)b * OO + o) * NN + nbase + nt + ns] * invl[o];
        }
        __syncthreads();
#pragma unroll 1
        for (int ns = 0; ns < 8; ns++) {
            int n = nbase + nt + ns;
            float2 x2 = *((const float2*)(Xb + (size_t)n * DD + 2 * t));
            unsigned long long x = pack2(x2.x, x2.y);
#pragma unroll
            for (int o = 0; o < OO; o++) {
                float w = wsh[ns][o];
                acc[o] = fma2(pack2(w, w), x, acc[o]);
            }
        }
    }
    float* yp = g_ypart + ((size_t)b * NCH3 + ch) * OO * DD;
#pragma unroll
    for (int o = 0; o < OO; o++) {
        float lo, hi; unpack2(acc[o], lo, hi);
        *((float2*)(yp + (size_t)o * DD + 2 * t)) = make_float2(lo, hi);
    }
}

// ---- K4: reduce partials, apply Wv per head, Wo, residual, LayerNorm ----
__global__ __launch_bounds__(256) void k4_final(const float* __restrict__ seed,
                                                const float* __restrict__ Wv,
                                                const float* __restrict__ bv,
                                                const float* __restrict__ Wo,
                                                const float* __restrict__ bo,
                                                const float* __restrict__ gamma,
                                                const float* __restrict__ beta,
                                                float* __restrict__ out) {
    int i = blockIdx.x;  // seed index
    int b = blockIdx.y;
    int t = threadIdx.x; // 256
    __shared__ float ysh[HH * DD];   // 16 KB
    __shared__ float presh[DD];
    __shared__ float red[256];

    // reduce y over chunks
    for (int idx = t; idx < HH * DD; idx += 256) {
        int h = idx >> 9, c = idx & 511;
        int o = i * HH + h;
        float s = 0.f;
        for (int ch = 0; ch < NCH3; ch++)
            s += g_ypart[(((size_t)b * NCH3 + ch) * OO + o) * DD + c];
        ysh[idx] = s;
    }
    __syncthreads();

    // pre[g] = bv[g] + Wv[g,:]·y[head(g)]
    for (int g = t; g < DD; g += 256) {
        int h = g >> 6;
        const float4* wr = (const float4*)(Wv + (size_t)g * DD);
        const float4* yr = (const float4*)(ysh + h * DD);
        float acc = 0.f;
#pragma unroll 4
        for (int c4 = 0; c4 < DD / 4; c4++) {
            float4 w4 = wr[c4], y4 = yr[c4];
            acc += w4.x * y4.x + w4.y * y4.y + w4.z * y4.z + w4.w * y4.w;
        }
        presh[g] = acc + bv[g];
    }
    __syncthreads();

    // z[g] = bo[g] + seed[i,g] + Wo[g,:]·pre
    float zv[2];
#pragma unroll
    for (int gi = 0; gi < 2; gi++) {
        int g = t + gi * 256;
        const float4* wr = (const float4*)(Wo + (size_t)g * DD);
        const float4* pr = (const float4*)presh;
        float acc = 0.f;
#pragma unroll 4
        for (int c4 = 0; c4 < DD / 4; c4++) {
            float4 w4 = wr[c4], p4 = pr[c4];
            acc += w4.x * p4.x + w4.y * p4.y + w4.z * p4.z + w4.w * p4.w;
        }
        zv[gi] = acc + bo[g] + seed[(size_t)i * DD + g];
    }

    // LayerNorm over 512
    red[t] = zv[0] + zv[1]; __syncthreads();
    for (int st = 128; st > 0; st >>= 1) { if (t < st) red[t] += red[t + st]; __syncthreads(); }
    float mu = red[0] * (1.0f / DD); __syncthreads();
    float d0 = zv[0] - mu, d1 = zv[1] - mu;
    red[t] = d0 * d0 + d1 * d1; __syncthreads();
    for (int st = 128; st > 0; st >>= 1) { if (t < st) red[t] += red[t + st]; __syncthreads(); }
    float rstd = rsqrtf(red[0] * (1.0f / DD) + 1e-6f);

    float* op = out + ((size_t)b * KSEED + i) * DD;
#pragma unroll
    for (int gi = 0; gi < 2; gi++) {
        int g = t + gi * 256;
        op[g] = (zv[gi] - mu) * rstd * gamma[g] + beta[g];
    }
}

extern "C" void kernel_launch(void* const* d_in, const int* in_sizes, int n_in,
                              void* d_out, int out_size) {
    const float* X     = (const float*)d_in[0];
    const float* seed  = (const float*)d_in[1];
    const float* Wq    = (const float*)d_in[2];
    const float* bq    = (const float*)d_in[3];
    const float* Wk    = (const float*)d_in[4];
    const float* bk    = (const float*)d_in[5];
    const float* Wv    = (const float*)d_in[6];
    const float* bv    = (const float*)d_in[7];
    const float* Wo    = (const float*)d_in[8];
    const float* bo    = (const float*)d_in[9];
    const float* gamma = (const float*)d_in[10];
    const float* beta  = (const float*)d_in[11];
    float* out = (float*)d_out;

    k0a_q<<<KSEED, DD>>>(seed, Wq, bq);
    k0b_P<<<HH, DD>>>(Wk, bk);
    k1_scores<<<dim3(NN / 64, BB), 256>>>(X);
    k2_softmax<<<BB * OO, 256>>>();
    k3_accum<<<dim3(NCH3, BB), 256>>>(X);
    k4_final<<<dim3(KSEED, BB), 256>>>(seed, Wv, bv, Wo, bo, gamma, beta, out);
}

// round 2
// speedup vs baseline: 1.1517x; 1.1517x over previous
#include <cuda_runtime.h>
#include <math.h>

#define BB 16
#define NN 8192
#define DD 512
#define HH 8
#define KSEED 4
#define OO 32            // KSEED*HH, o = i*8 + h
#define NCH3 16          // chunks per batch in K3 (512 n each)

// ---- scratch (no allocations allowed; __device__ globals) ----
__device__ float g_q[KSEED * DD];
__device__ float g_P[OO * DD];
__device__ float g_c0[OO];
__device__ float g_S[(size_t)BB * OO * NN];      // scores, then exp() in place
__device__ float g_invl[BB * OO];
__device__ float g_ypart[(size_t)BB * NCH3 * OO * DD];

// ---- packed f32x2 helpers ----
__device__ __forceinline__ unsigned long long pack2(float lo, float hi) {
    unsigned long long r;
    asm("mov.b64 %0, {%1,%2};" : "=l"(r)
        : "r"(__float_as_uint(lo)), "r"(__float_as_uint(hi)));
    return r;
}
__device__ __forceinline__ void unpack2(unsigned long long v, float& lo, float& hi) {
    unsigned a, b;
    asm("mov.b64 {%0,%1}, %2;" : "=r"(a), "=r"(b) : "l"(v));
    lo = __uint_as_float(a); hi = __uint_as_float(b);
}
__device__ __forceinline__ unsigned long long fma2(unsigned long long a,
                                                   unsigned long long b,
                                                   unsigned long long c) {
    unsigned long long d;
    asm("fma.rn.f32x2 %0, %1, %2, %3;" : "=l"(d) : "l"(a), "l"(b), "l"(c));
    return d;
}

// ---- K0a: q[i,c] = sum_e seed[i,e]*Wq[c,e] + bq[c] ----
__global__ void k0a_q(const float* __restrict__ seed,
                      const float* __restrict__ Wq,
                      const float* __restrict__ bq) {
    int i = blockIdx.x;      // 4 blocks
    int c = threadIdx.x;     // 512 threads
    const float4* w  = (const float4*)(Wq + (size_t)c * DD);
    const float4* sd = (const float4*)(seed + (size_t)i * DD);
    float acc = 0.f;
#pragma unroll 4
    for (int e4 = 0; e4 < DD / 4; e4++) {
        float4 a = w[e4], s4 = sd[e4];
        acc += a.x * s4.x + a.y * s4.y + a.z * s4.z + a.w * s4.w;
    }
    g_q[i * DD + c] = acc + bq[c];
}

// ---- K0b: P[(i*8+h),c] = (1/8) sum_d q[i,h*64+d] * Wk[h*64+d, c]; c0 likewise ----
__global__ void k0b_P(const float* __restrict__ Wk,
                      const float* __restrict__ bk) {
    __shared__ float qsh[KSEED * 64];
    int h = blockIdx.x;      // 8 blocks
    int c = threadIdx.x;     // 512 threads
    if (c < KSEED * 64) {
        int i = c >> 6, d = c & 63;
        qsh[c] = g_q[i * DD + h * 64 + d];
    }
    __syncthreads();
    float acc[KSEED] = {0.f, 0.f, 0.f, 0.f};
    for (int d = 0; d < 64; d++) {
        float w = Wk[(size_t)(h * 64 + d) * DD + c];
#pragma unroll
        for (int i = 0; i < KSEED; i++) acc[i] += qsh[i * 64 + d] * w;
    }
#pragma unroll
    for (int i = 0; i < KSEED; i++)
        g_P[(size_t)(i * HH + h) * DD + c] = acc[i] * 0.125f;
    if (c < KSEED) {
        float a = 0.f;
        for (int d = 0; d < 64; d++) a += qsh[c * 64 + d] * bk[h * 64 + d];
        g_c0[c * HH + h] = a * 0.125f;
    }
}

// ---- K1': scores s[b,o,n] = P[o]·X[b,n] + c0[o], register-tiled ----
// block: 256 thr = 8 warps. warp w: o-base = (w&3)*8, n-half = (w>>2)*32.
// lane = n within half. acc2[8] over c-pairs, no cross-lane reduction.
#define XROW 68   // padded row stride (floats) for conflict-free LDS.128
__global__ __launch_bounds__(256, 3) void k1_scores(const float* __restrict__ X) {
    __shared__ float Xs[64 * XROW];      // ~17.4 KB
    __shared__ float Ps[OO * 64];        // 8 KB  (P subtile [o][64c])
    int b = blockIdx.y;
    int nbase = blockIdx.x * 64;
    int t = threadIdx.x;
    int w = t >> 5, lane = t & 31;
    int obase = (w & 3) * 8;
    int nloc = ((w >> 2) << 5) + lane;   // 0..63

    unsigned long long acc2[8];
#pragma unroll
    for (int j = 0; j < 8; j++) acc2[j] = 0ULL;

    const float* Xb = X + ((size_t)b * NN + nbase) * DD;

    for (int k = 0; k < 8; k++) {
        int csub = k * 64;
        __syncthreads();
        // load P subtile [32 o][64 c]
        {
            float4* pd = (float4*)Ps;
#pragma unroll
            for (int r = 0; r < 2; r++) {
                int idx = t + r * 256;           // 0..511
                int o = idx >> 4, q = idx & 15;
                pd[o * 16 + q] = *(const float4*)(g_P + (size_t)o * DD + csub + q * 4);
            }
        }
        // load X subtile [64 n][64 c] -> padded rows
#pragma unroll
        for (int r = 0; r < 4; r++) {
            int idx = t + r * 256;               // 0..1023
            int n = idx >> 4, q = idx & 15;
            float4 v = *(const float4*)(Xb + (size_t)n * DD + csub + q * 4);
            *(float4*)(Xs + n * XROW + q * 4) = v;
        }
        __syncthreads();

        const float* xrow = Xs + nloc * XROW;
        const float4* psf = (const float4*)Ps;
#pragma unroll 4
        for (int cq = 0; cq < 16; cq++) {
            float4 x4 = *(const float4*)(xrow + cq * 4);
            unsigned long long x01 = pack2(x4.x, x4.y);
            unsigned long long x23 = pack2(x4.z, x4.w);
#pragma unroll
            for (int j = 0; j < 8; j++) {
                float4 p4 = psf[(obase + j) * 16 + cq];
                acc2[j] = fma2(pack2(p4.x, p4.y), x01, acc2[j]);
                acc2[j] = fma2(pack2(p4.z, p4.w), x23, acc2[j]);
            }
        }
    }
#pragma unroll
    for (int j = 0; j < 8; j++) {
        int o = obase + j;
        float lo, hi; unpack2(acc2[j], lo, hi);
        g_S[((size_t)b * OO + o) * NN + nbase + nloc] = lo + hi + g_c0[o];
    }
}

// ---- K2: softmax stats per (b,o): s <- exp(s-m); invl = 1/sum ----
__global__ __launch_bounds__(256) void k2_softmax() {
    int bo = blockIdx.x;             // 512 blocks
    float* s = g_S + (size_t)bo * NN;
    int t = threadIdx.x;
    __shared__ float red[256];
    float m = -1e30f;
    for (int n = t; n < NN; n += 256) m = fmaxf(m, s[n]);
    red[t] = m; __syncthreads();
    for (int st = 128; st > 0; st >>= 1) {
        if (t < st) red[t] = fmaxf(red[t], red[t + st]);
        __syncthreads();
    }
    m = red[0]; __syncthreads();
    float sum = 0.f;
    for (int n = t; n < NN; n += 256) {
        float e = __expf(s[n] - m);
        s[n] = e;
        sum += e;
    }
    red[t] = sum; __syncthreads();
    for (int st = 128; st > 0; st >>= 1) {
        if (t < st) red[t] += red[t + st];
        __syncthreads();
    }
    if (t == 0) g_invl[bo] = 1.0f / red[0];
}

// ---- K3': partial pooled sums, register-tiled ----
// block 256 thr = 8 warps. warp w -> o-set w*4..w*4+3; lane -> c strip [16ℓ,16ℓ+16).
// chunk = 512 n per block, staged in smem 16 n at a time.
__global__ __launch_bounds__(256, 2) void k3_accum(const float* __restrict__ X) {
    __shared__ float Xs[16 * DD];    // 32 KB
    int b = blockIdx.y;
    int ch = blockIdx.x;             // 0..15
    int t = threadIdx.x;
    int w = t >> 5, lane = t & 31;
    int obase = w * 4;
    int cbase = lane * 16;

    float iv[4];
#pragma unroll
    for (int j = 0; j < 4; j++) iv[j] = g_invl[b * OO + obase + j];

    unsigned long long acc2[4][8];
#pragma unroll
    for (int j = 0; j < 4; j++)
#pragma unroll
        for (int q = 0; q < 8; q++) acc2[j][q] = 0ULL;

    const float* Xb = X + (size_t)b * NN * DD;
    int nch = ch * 512;

    for (int st = 0; st < 32; st++) {
        int nbase = nch + st * 16;
        __syncthreads();
#pragma unroll
        for (int r = 0; r < 8; r++) {
            int idx = t + r * 256;               // 0..2047 float4s
            int n = idx >> 7, q = idx & 127;
            *(float4*)(Xs + n * DD + q * 4) =
                *(const float4*)(Xb + (size_t)(nbase + n) * DD + q * 4);
        }
        __syncthreads();

#pragma unroll 2
        for (int n2 = 0; n2 < 16; n2++) {
            int n = nbase + n2;
            unsigned long long pk[4];
#pragma unroll
            for (int j = 0; j < 4; j++) {
                float p = g_S[((size_t)b * OO + obase + j) * NN + n] * iv[j];
                pk[j] = pack2(p, p);
            }
            const float* xr = Xs + n2 * DD + cbase;
#pragma unroll
            for (int q = 0; q < 4; q++) {
                float4 x4 = *(const float4*)(xr + q * 4);
                unsigned long long x01 = pack2(x4.x, x4.y);
                unsigned long long x23 = pack2(x4.z, x4.w);
#pragma unroll
                for (int j = 0; j < 4; j++) {
                    acc2[j][2 * q]     = fma2(pk[j], x01, acc2[j][2 * q]);
                    acc2[j][2 * q + 1] = fma2(pk[j], x23, acc2[j][2 * q + 1]);
                }
            }
        }
    }

    float* yp = g_ypart + (((size_t)b * NCH3 + ch) * OO) * DD;
#pragma unroll
    for (int j = 0; j < 4; j++) {
#pragma unroll
        for (int q = 0; q < 4; q++) {
            float a, bq_, c_, d_;
            unpack2(acc2[j][2 * q], a, bq_);
            unpack2(acc2[j][2 * q + 1], c_, d_);
            *(float4*)(yp + (size_t)(obase + j) * DD + cbase + q * 4) =
                make_float4(a, bq_, c_, d_);
        }
    }
}

// ---- K4: reduce partials, apply Wv per head, Wo, residual, LayerNorm ----
__global__ __launch_bounds__(256) void k4_final(const float* __restrict__ seed,
                                                const float* __restrict__ Wv,
                                                const float* __restrict__ bv,
                                                const float* __restrict__ Wo,
                                                const float* __restrict__ bo,
                                                const float* __restrict__ gamma,
                                                const float* __restrict__ beta,
                                                float* __restrict__ out) {
    int i = blockIdx.x;  // seed index
    int b = blockIdx.y;
    int t = threadIdx.x; // 256
    __shared__ float ysh[HH * DD];   // 16 KB
    __shared__ float presh[DD];
    __shared__ float red[256];

    // reduce y over chunks
    for (int idx = t; idx < HH * DD; idx += 256) {
        int h = idx >> 9, c = idx & 511;
        int o = i * HH + h;
        float s = 0.f;
        for (int ch = 0; ch < NCH3; ch++)
            s += g_ypart[(((size_t)b * NCH3 + ch) * OO + o) * DD + c];
        ysh[idx] = s;
    }
    __syncthreads();

    // pre[g] = bv[g] + Wv[g,:]·y[head(g)]
    for (int g = t; g < DD; g += 256) {
        int h = g >> 6;
        const float4* wr = (const float4*)(Wv + (size_t)g * DD);
        const float4* yr = (const float4*)(ysh + h * DD);
        float acc = 0.f;
#pragma unroll 4
        for (int c4 = 0; c4 < DD / 4; c4++) {
            float4 w4 = wr[c4], y4 = yr[c4];
            acc += w4.x * y4.x + w4.y * y4.y + w4.z * y4.z + w4.w * y4.w;
        }
        presh[g] = acc + bv[g];
    }
    __syncthreads();

    // z[g] = bo[g] + seed[i,g] + Wo[g,:]·pre
    float zv[2];
#pragma unroll
    for (int gi = 0; gi < 2; gi++) {
        int g = t + gi * 256;
        const float4* wr = (const float4*)(Wo + (size_t)g * DD);
        const float4* pr = (const float4*)presh;
        float acc = 0.f;
#pragma unroll 4
        for (int c4 = 0; c4 < DD / 4; c4++) {
            float4 w4 = wr[c4], p4 = pr[c4];
            acc += w4.x * p4.x + w4.y * p4.y + w4.z * p4.z + w4.w * p4.w;
        }
        zv[gi] = acc + bo[g] + seed[(size_t)i * DD + g];
    }

    // LayerNorm over 512
    red[t] = zv[0] + zv[1]; __syncthreads();
    for (int st = 128; st > 0; st >>= 1) { if (t < st) red[t] += red[t + st]; __syncthreads(); }
    float mu = red[0] * (1.0f / DD); __syncthreads();
    float d0 = zv[0] - mu, d1 = zv[1] - mu;
    red[t] = d0 * d0 + d1 * d1; __syncthreads();
    for (int st = 128; st > 0; st >>= 1) { if (t < st) red[t] += red[t + st]; __syncthreads(); }
    float rstd = rsqrtf(red[0] * (1.0f / DD) + 1e-6f);

    float* op = out + ((size_t)b * KSEED + i) * DD;
#pragma unroll
    for (int gi = 0; gi < 2; gi++) {
        int g = t + gi * 256;
        op[g] = (zv[gi] - mu) * rstd * gamma[g] + beta[g];
    }
}

extern "C" void kernel_launch(void* const* d_in, const int* in_sizes, int n_in,
                              void* d_out, int out_size) {
    const float* X     = (const float*)d_in[0];
    const float* seed  = (const float*)d_in[1];
    const float* Wq    = (const float*)d_in[2];
    const float* bq    = (const float*)d_in[3];
    const float* Wk    = (const float*)d_in[4];
    const float* bk    = (const float*)d_in[5];
    const float* Wv    = (const float*)d_in[6];
    const float* bv    = (const float*)d_in[7];
    const float* Wo    = (const float*)d_in[8];
    const float* bo    = (const float*)d_in[9];
    const float* gamma = (const float*)d_in[10];
    const float* beta  = (const float*)d_in[11];
    float* out = (float*)d_out;

    k0a_q<<<KSEED, DD>>>(seed, Wq, bq);
    k0b_P<<<HH, DD>>>(Wk, bk);
    k1_scores<<<dim3(NN / 64, BB), 256>>>(X);
    k2_softmax<<<BB * OO, 256>>>();
    k3_accum<<<dim3(NCH3, BB), 256>>>(X);
    k4_final<<<dim3(KSEED, BB), 256>>>(seed, Wv, bv, Wo, bo, gamma, beta, out);
}

// round 3
// speedup vs baseline: 1.5047x; 1.3065x over previous
#include <cuda_runtime.h>
#include <math.h>

#define BB 16
#define NN 8192
#define DD 512
#define HH 8
#define KSEED 4
#define OO 32            // KSEED*HH, o = i*8 + h
#define NCH3 16          // chunks per batch in K3 (512 n each)
#define XROW 68          // padded X row stride in K1 smem

// ---- scratch (no allocations allowed; __device__ globals) ----
__device__ float g_q[KSEED * DD];
__device__ float g_P[OO * DD];
__device__ float g_c0[OO];
__device__ float g_S[(size_t)BB * OO * NN];      // raw scores -> exp() in place
__device__ float g_W[(size_t)BB * NN * OO];      // normalized transposed weights
__device__ float g_invl[BB * OO];
__device__ float g_ypart[(size_t)BB * NCH3 * OO * DD];

// ---- packed f32x2 helpers ----
__device__ __forceinline__ unsigned long long pack2(float lo, float hi) {
    unsigned long long r;
    asm("mov.b64 %0, {%1,%2};" : "=l"(r)
        : "r"(__float_as_uint(lo)), "r"(__float_as_uint(hi)));
    return r;
}
__device__ __forceinline__ void unpack2(unsigned long long v, float& lo, float& hi) {
    unsigned a, b;
    asm("mov.b64 {%0,%1}, %2;" : "=r"(a), "=r"(b) : "l"(v));
    lo = __uint_as_float(a); hi = __uint_as_float(b);
}
__device__ __forceinline__ unsigned long long fma2(unsigned long long a,
                                                   unsigned long long b,
                                                   unsigned long long c) {
    unsigned long long d;
    asm("fma.rn.f32x2 %0, %1, %2, %3;" : "=l"(d) : "l"(a), "l"(b), "l"(c));
    return d;
}

// ---- K0a: q[i,c] = sum_e seed[i,e]*Wq[c,e] + bq[c] ----
__global__ void k0a_q(const float* __restrict__ seed,
                      const float* __restrict__ Wq,
                      const float* __restrict__ bq) {
    int i = blockIdx.x;      // 4 blocks
    int c = threadIdx.x;     // 512 threads
    const float4* w  = (const float4*)(Wq + (size_t)c * DD);
    const float4* sd = (const float4*)(seed + (size_t)i * DD);
    float acc = 0.f;
#pragma unroll 4
    for (int e4 = 0; e4 < DD / 4; e4++) {
        float4 a = w[e4], s4 = sd[e4];
        acc += a.x * s4.x + a.y * s4.y + a.z * s4.z + a.w * s4.w;
    }
    g_q[i * DD + c] = acc + bq[c];
}

// ---- K0b: P[(i*8+h),c] = (1/8) sum_d q[i,h*64+d] * Wk[h*64+d, c]; c0 likewise ----
__global__ void k0b_P(const float* __restrict__ Wk,
                      const float* __restrict__ bk) {
    __shared__ float qsh[KSEED * 64];
    int h = blockIdx.x;      // 8 blocks
    int c = threadIdx.x;     // 512 threads
    if (c < KSEED * 64) {
        int i = c >> 6, d = c & 63;
        qsh[c] = g_q[i * DD + h * 64 + d];
    }
    __syncthreads();
    float acc[KSEED] = {0.f, 0.f, 0.f, 0.f};
    for (int d = 0; d < 64; d++) {
        float w = Wk[(size_t)(h * 64 + d) * DD + c];
#pragma unroll
        for (int i = 0; i < KSEED; i++) acc[i] += qsh[i * 64 + d] * w;
    }
#pragma unroll
    for (int i = 0; i < KSEED; i++)
        g_P[(size_t)(i * HH + h) * DD + c] = acc[i] * 0.125f;
    if (c < KSEED) {
        float a = 0.f;
        for (int d = 0; d < 64; d++) a += qsh[c * 64 + d] * bk[h * 64 + d];
        g_c0[c * HH + h] = a * 0.125f;
    }
}

// ---- K1: scores s[b,o,n] = P[o]·X[b,n] + c0[o] ----
// block tile: 256 n x 32 o. 8 warps: warp w -> o-group (w&3)*8, n-half (w>>2)*128.
// thread: 8 o x 4 n accumulators (ull, lo/hi = even/odd c). No packing movs.
__global__ __launch_bounds__(256, 2) void k1_scores(const float* __restrict__ X) {
    extern __shared__ float Xs[];                 // 256 * 68 floats = 68 KB
    __shared__ __align__(16) float Ps[OO * 64];   // 8 KB
    __shared__ float c0s[OO];
    int b = blockIdx.y;
    int nbase = blockIdx.x * 256;
    int t = threadIdx.x;
    int w = t >> 5, lane = t & 31;
    int obase = (w & 3) * 8;
    int nh = (w >> 2) * 128;       // thread n's: nh + lane + 32*m

    if (t < OO) c0s[t] = g_c0[t];

    unsigned long long acc[8][4];
#pragma unroll
    for (int j = 0; j < 8; j++)
#pragma unroll
        for (int m = 0; m < 4; m++) acc[j][m] = 0ULL;

    const float* Xb = X + ((size_t)b * NN + nbase) * DD;

#pragma unroll 1
    for (int k = 0; k < 8; k++) {
        int csub = k * 64;
        __syncthreads();
        // stage P subtile [32 o][64 c]
#pragma unroll
        for (int r = 0; r < 2; r++) {
            int idx = t + r * 256;               // 0..511
            int o = idx >> 4, q = idx & 15;
            *(float4*)(Ps + o * 64 + q * 4) =
                *(const float4*)(g_P + (size_t)o * DD + csub + q * 4);
        }
        // stage X subtile [256 n][64 c] into padded rows
#pragma unroll
        for (int r = 0; r < 16; r++) {
            int idx = t + r * 256;               // 0..4095
            int n = idx >> 4, q = idx & 15;
            *(float4*)(Xs + n * XROW + q * 4) =
                *(const float4*)(Xb + (size_t)n * DD + csub + q * 4);
        }
        __syncthreads();

#pragma unroll 4
        for (int cq = 0; cq < 16; cq++) {
            ulonglong2 xv[4];
#pragma unroll
            for (int m = 0; m < 4; m++)
                xv[m] = *(const ulonglong2*)(Xs + (nh + lane + 32 * m) * XROW + cq * 4);
#pragma unroll
            for (int j = 0; j < 8; j++) {
                ulonglong2 pv = *(const ulonglong2*)(Ps + (obase + j) * 64 + cq * 4);
#pragma unroll
                for (int m = 0; m < 4; m++) {
                    acc[j][m] = fma2(pv.x, xv[m].x, acc[j][m]);
                    acc[j][m] = fma2(pv.y, xv[m].y, acc[j][m]);
                }
            }
        }
    }

#pragma unroll
    for (int j = 0; j < 8; j++) {
        int o = obase + j;
        float* sp = g_S + ((size_t)b * OO + o) * NN + nbase + nh + lane;
#pragma unroll
        for (int m = 0; m < 4; m++) {
            float lo, hi; unpack2(acc[j][m], lo, hi);
            sp[32 * m] = lo + hi + c0s[o];
        }
    }
}

// ---- K2: softmax stats per (b,o): s <- exp(s-m); invl = 1/sum ----
__global__ __launch_bounds__(256) void k2_softmax() {
    int bo = blockIdx.x;             // 512 blocks
    float* s = g_S + (size_t)bo * NN;
    int t = threadIdx.x;
    __shared__ float red[256];
    float m = -1e30f;
    for (int n = t; n < NN; n += 256) m = fmaxf(m, s[n]);
    red[t] = m; __syncthreads();
    for (int st = 128; st > 0; st >>= 1) {
        if (t < st) red[t] = fmaxf(red[t], red[t + st]);
        __syncthreads();
    }
    m = red[0]; __syncthreads();
    float sum = 0.f;
    for (int n = t; n < NN; n += 256) {
        float e = __expf(s[n] - m);
        s[n] = e;
        sum += e;
    }
    red[t] = sum; __syncthreads();
    for (int st = 128; st > 0; st >>= 1) {
        if (t < st) red[t] += red[t + st];
        __syncthreads();
    }
    if (t == 0) g_invl[bo] = 1.0f / red[0];
}

// ---- K2b: transpose + normalize: g_W[b][n][o] = g_S[b][o][n] * invl[b][o] ----
__global__ __launch_bounds__(256) void k2b_transpose() {
    __shared__ float sh[64][33];
    __shared__ float ivs[OO];
    int b = blockIdx.y;
    int nbase = blockIdx.x * 64;
    int t = threadIdx.x;
    if (t < OO) ivs[t] = g_invl[b * OO + t];
    __syncthreads();
#pragma unroll
    for (int r = 0; r < 8; r++) {
        int idx = t + r * 256;           // 0..2047
        int o = idx >> 6, nn = idx & 63;
        sh[nn][o] = g_S[((size_t)b * OO + o) * NN + nbase + nn];
    }
    __syncthreads();
#pragma unroll
    for (int r = 0; r < 8; r++) {
        int idx = t + r * 256;
        int nn = idx >> 5, o = idx & 31;
        g_W[((size_t)b * NN + nbase + nn) * OO + o] = sh[nn][o] * ivs[o];
    }
}

// ---- K3: partial pooled sums y_part[b,ch,o,c] = sum_n w[b,n,o] * X[b,n,c] ----
// 8 warps -> 4 o each (obase = w*4); lane's 16 c spread as 4 float4s at lane*4+128k.
__global__ __launch_bounds__(256, 2) void k3_accum(const float* __restrict__ X) {
    __shared__ __align__(16) float Xs[16 * DD];    // 32 KB
    int b = blockIdx.y;
    int ch = blockIdx.x;             // 0..15
    int t = threadIdx.x;
    int w = t >> 5, lane = t & 31;
    int obase = w * 4;

    unsigned long long acc[4][8];
#pragma unroll
    for (int j = 0; j < 4; j++)
#pragma unroll
        for (int q = 0; q < 8; q++) acc[j][q] = 0ULL;

    const float* Xb = X + (size_t)b * NN * DD;
    const float* Wb = g_W + (size_t)b * NN * OO;
    int nch = ch * 512;

#pragma unroll 1
    for (int st = 0; st < 32; st++) {
        int nbase = nch + st * 16;
        __syncthreads();
#pragma unroll
        for (int r = 0; r < 8; r++) {
            int idx = t + r * 256;               // 0..2047 float4s
            int n = idx >> 7, q = idx & 127;
            *(float4*)(Xs + n * DD + q * 4) =
                *(const float4*)(Xb + (size_t)(nbase + n) * DD + q * 4);
        }
        __syncthreads();

#pragma unroll 2
        for (int n2 = 0; n2 < 16; n2++) {
            float4 w4 = *(const float4*)(Wb + (size_t)(nbase + n2) * OO + obase);
            unsigned long long pw[4];
            pw[0] = pack2(w4.x, w4.x);
            pw[1] = pack2(w4.y, w4.y);
            pw[2] = pack2(w4.z, w4.z);
            pw[3] = pack2(w4.w, w4.w);
#pragma unroll
            for (int kk = 0; kk < 4; kk++) {
                ulonglong2 xv = *(const ulonglong2*)(Xs + n2 * DD + kk * 128 + lane * 4);
#pragma unroll
                for (int j = 0; j < 4; j++) {
                    acc[j][2 * kk]     = fma2(pw[j], xv.x, acc[j][2 * kk]);
                    acc[j][2 * kk + 1] = fma2(pw[j], xv.y, acc[j][2 * kk + 1]);
                }
            }
        }
    }

    float* yp = g_ypart + (((size_t)b * NCH3 + ch) * OO) * DD;
#pragma unroll
    for (int j = 0; j < 4; j++) {
#pragma unroll
        for (int kk = 0; kk < 4; kk++) {
            float a, b2, c2, d2;
            unpack2(acc[j][2 * kk], a, b2);
            unpack2(acc[j][2 * kk + 1], c2, d2);
            *(float4*)(yp + (size_t)(obase + j) * DD + kk * 128 + lane * 4) =
                make_float4(a, b2, c2, d2);
        }
    }
}

// ---- K4: reduce partials, apply Wv per head, Wo, residual, LayerNorm ----
__global__ __launch_bounds__(256) void k4_final(const float* __restrict__ seed,
                                                const float* __restrict__ Wv,
                                                const float* __restrict__ bv,
                                                const float* __restrict__ Wo,
                                                const float* __restrict__ bo,
                                                const float* __restrict__ gamma,
                                                const float* __restrict__ beta,
                                                float* __restrict__ out) {
    int i = blockIdx.x;  // seed index
    int b = blockIdx.y;
    int t = threadIdx.x; // 256
    __shared__ float ysh[HH * DD];   // 16 KB
    __shared__ float presh[DD];
    __shared__ float red[256];

    // reduce y over chunks
    for (int idx = t; idx < HH * DD; idx += 256) {
        int h = idx >> 9, c = idx & 511;
        int o = i * HH + h;
        float s = 0.f;
        for (int ch = 0; ch < NCH3; ch++)
            s += g_ypart[(((size_t)b * NCH3 + ch) * OO + o) * DD + c];
        ysh[idx] = s;
    }
    __syncthreads();

    // pre[g] = bv[g] + Wv[g,:]·y[head(g)]
    for (int g = t; g < DD; g += 256) {
        int h = g >> 6;
        const float4* wr = (const float4*)(Wv + (size_t)g * DD);
        const float4* yr = (const float4*)(ysh + h * DD);
        float acc = 0.f;
#pragma unroll 4
        for (int c4 = 0; c4 < DD / 4; c4++) {
            float4 w4 = wr[c4], y4 = yr[c4];
            acc += w4.x * y4.x + w4.y * y4.y + w4.z * y4.z + w4.w * y4.w;
        }
        presh[g] = acc + bv[g];
    }
    __syncthreads();

    // z[g] = bo[g] + seed[i,g] + Wo[g,:]·pre
    float zv[2];
#pragma unroll
    for (int gi = 0; gi < 2; gi++) {
        int g = t + gi * 256;
        const float4* wr = (const float4*)(Wo + (size_t)g * DD);
        const float4* pr = (const float4*)presh;
        float acc = 0.f;
#pragma unroll 4
        for (int c4 = 0; c4 < DD / 4; c4++) {
            float4 w4 = wr[c4], p4 = pr[c4];
            acc += w4.x * p4.x + w4.y * p4.y + w4.z * p4.z + w4.w * p4.w;
        }
        zv[gi] = acc + bo[g] + seed[(size_t)i * DD + g];
    }

    // LayerNorm over 512
    red[t] = zv[0] + zv[1]; __syncthreads();
    for (int st = 128; st > 0; st >>= 1) { if (t < st) red[t] += red[t + st]; __syncthreads(); }
    float mu = red[0] * (1.0f / DD); __syncthreads();
    float d0 = zv[0] - mu, d1 = zv[1] - mu;
    red[t] = d0 * d0 + d1 * d1; __syncthreads();
    for (int st = 128; st > 0; st >>= 1) { if (t < st) red[t] += red[t + st]; __syncthreads(); }
    float rstd = rsqrtf(red[0] * (1.0f / DD) + 1e-6f);

    float* op = out + ((size_t)b * KSEED + i) * DD;
#pragma unroll
    for (int gi = 0; gi < 2; gi++) {
        int g = t + gi * 256;
        op[g] = (zv[gi] - mu) * rstd * gamma[g] + beta[g];
    }
}

extern "C" void kernel_launch(void* const* d_in, const int* in_sizes, int n_in,
                              void* d_out, int out_size) {
    const float* X     = (const float*)d_in[0];
    const float* seed  = (const float*)d_in[1];
    const float* Wq    = (const float*)d_in[2];
    const float* bq    = (const float*)d_in[3];
    const float* Wk    = (const float*)d_in[4];
    const float* bk    = (const float*)d_in[5];
    const float* Wv    = (const float*)d_in[6];
    const float* bv    = (const float*)d_in[7];
    const float* Wo    = (const float*)d_in[8];
    const float* bo    = (const float*)d_in[9];
    const float* gamma = (const float*)d_in[10];
    const float* beta  = (const float*)d_in[11];
    float* out = (float*)d_out;

    int xs_bytes = 256 * XROW * sizeof(float);   // 69632
    cudaFuncSetAttribute(k1_scores, cudaFuncAttributeMaxDynamicSharedMemorySize, xs_bytes);

    k0a_q<<<KSEED, DD>>>(seed, Wq, bq);
    k0b_P<<<HH, DD>>>(Wk, bk);
    k1_scores<<<dim3(NN / 256, BB), 256, xs_bytes>>>(X);
    k2_softmax<<<BB * OO, 256>>>();
    k2b_transpose<<<dim3(NN / 64, BB), 256>>>();
    k3_accum<<<dim3(NCH3, BB), 256>>>(X);
    k4_final<<<dim3(KSEED, BB), 256>>>(seed, Wv, bv, Wo, bo, gamma, beta, out);
}

// round 4
// speedup vs baseline: 1.8147x; 1.2060x over previous
#include <cuda_runtime.h>
#include <math.h>

#define BB 16
#define NN 8192
#define DD 512
#define HH 8
#define KSEED 4
#define OO 32            // KSEED*HH, o = i*8 + h
#define NCH3 16          // chunks per batch in K3 (512 n each)

// ---- scratch (no allocations allowed; __device__ globals) ----
__device__ float g_q[KSEED * DD];
__device__ float g_P[OO * DD];
__device__ float g_c0[OO];
__device__ float g_S[(size_t)BB * OO * NN];        // raw scores
__device__ float g_m[BB * OO];
__device__ float g_invl[BB * OO];
__device__ float g_Wd[(size_t)BB * NN * OO * 2];   // normalized, transposed, duplicated
__device__ float g_ypart[(size_t)BB * NCH3 * OO * DD];

// ---- packed f32x2 helpers ----
__device__ __forceinline__ unsigned long long fma2(unsigned long long a,
                                                   unsigned long long b,
                                                   unsigned long long c) {
    unsigned long long d;
    asm("fma.rn.f32x2 %0, %1, %2, %3;" : "=l"(d) : "l"(a), "l"(b), "l"(c));
    return d;
}
__device__ __forceinline__ void unpack2(unsigned long long v, float& lo, float& hi) {
    unsigned a, b;
    asm("mov.b64 {%0,%1}, %2;" : "=r"(a), "=r"(b) : "l"(v));
    lo = __uint_as_float(a); hi = __uint_as_float(b);
}

// ---- cp.async helpers ----
__device__ __forceinline__ void cp16(float* dst_smem, const float* src) {
    unsigned d = (unsigned)__cvta_generic_to_shared(dst_smem);
    asm volatile("cp.async.cg.shared.global [%0], [%1], 16;\n" :: "r"(d), "l"(src));
}
#define CP_COMMIT() asm volatile("cp.async.commit_group;\n" ::: "memory")
#define CP_WAIT(n)  asm volatile("cp.async.wait_group %0;\n" :: "n"(n) : "memory")

// ---- K0a: q[i,c] = sum_e seed[i,e]*Wq[c,e] + bq[c] ----
__global__ void k0a_q(const float* __restrict__ seed,
                      const float* __restrict__ Wq,
                      const float* __restrict__ bq) {
    int i = blockIdx.x;      // 4 blocks
    int c = threadIdx.x;     // 512 threads
    const float4* w  = (const float4*)(Wq + (size_t)c * DD);
    const float4* sd = (const float4*)(seed + (size_t)i * DD);
    float acc = 0.f;
#pragma unroll 4
    for (int e4 = 0; e4 < DD / 4; e4++) {
        float4 a = w[e4], s4 = sd[e4];
        acc += a.x * s4.x + a.y * s4.y + a.z * s4.z + a.w * s4.w;
    }
    g_q[i * DD + c] = acc + bq[c];
}

// ---- K0b: P[(i*8+h),c] = (1/8) sum_d q[i,h*64+d] * Wk[h*64+d, c]; c0 likewise ----
__global__ void k0b_P(const float* __restrict__ Wk,
                      const float* __restrict__ bk) {
    __shared__ float qsh[KSEED * 64];
    int h = blockIdx.x;      // 8 blocks
    int c = threadIdx.x;     // 512 threads
    if (c < KSEED * 64) {
        int i = c >> 6, d = c & 63;
        qsh[c] = g_q[i * DD + h * 64 + d];
    }
    __syncthreads();
    float acc[KSEED] = {0.f, 0.f, 0.f, 0.f};
    for (int d = 0; d < 64; d++) {
        float w = Wk[(size_t)(h * 64 + d) * DD + c];
#pragma unroll
        for (int i = 0; i < KSEED; i++) acc[i] += qsh[i * 64 + d] * w;
    }
#pragma unroll
    for (int i = 0; i < KSEED; i++)
        g_P[(size_t)(i * HH + h) * DD + c] = acc[i] * 0.125f;
    if (c < KSEED) {
        float a = 0.f;
        for (int d = 0; d < 64; d++) a += qsh[c * 64 + d] * bk[h * 64 + d];
        g_c0[c * HH + h] = a * 0.125f;
    }
}

// ---- K1: scores s[b,o,n] = P[o]·X[b,n] + c0[o] ----
// 256n x 32o block tile; 16 stages of 32 c; cp.async double-buffered.
// warp w: o-group (w&3)*8, n-half (w>>2)*128; thread: 8o x 4n acc.
#define K1_XROW 36
#define K1_XBUF (256 * K1_XROW)    // 9216 floats
#define K1_PBUF (OO * 32)          // 1024 floats
__global__ __launch_bounds__(256, 2) void k1_scores(const float* __restrict__ X) {
    extern __shared__ float sh[];
    float* Xsb[2] = { sh, sh + K1_XBUF };
    float* Psb[2] = { sh + 2 * K1_XBUF, sh + 2 * K1_XBUF + K1_PBUF };
    __shared__ float c0s[OO];

    int b = blockIdx.y;
    int nbase = blockIdx.x * 256;
    int t = threadIdx.x;
    int w = t >> 5, lane = t & 31;
    int obase = (w & 3) * 8;
    int nh = (w >> 2) * 128;

    if (t < OO) c0s[t] = g_c0[t];

    const float* Xb = X + ((size_t)b * NN + nbase) * DD;

    // stage loader: c-range [k*32, k*32+32)
    auto stage = [&](int k, int buf) {
        float* xd = Xsb[buf];
        float* pd = Psb[buf];
        int csub = k * 32;
#pragma unroll
        for (int i = 0; i < 8; i++) {
            int idx = t + i * 256;              // 0..2047
            int row = idx >> 3, ck = idx & 7;
            cp16(xd + row * K1_XROW + ck * 4,
                 Xb + (size_t)row * DD + csub + ck * 4);
        }
        {
            int o = t >> 3, ck = t & 7;
            cp16(pd + o * 32 + ck * 4,
                 g_P + (size_t)o * DD + csub + ck * 4);
        }
    };

    unsigned long long acc[8][4];
#pragma unroll
    for (int j = 0; j < 8; j++)
#pragma unroll
        for (int m = 0; m < 4; m++) acc[j][m] = 0ULL;

    stage(0, 0);
    CP_COMMIT();

#pragma unroll 1
    for (int k = 0; k < 16; k++) {
        __syncthreads();                 // everyone done with buffer being overwritten
        if (k + 1 < 16) {
            stage(k + 1, (k + 1) & 1);
            CP_COMMIT();
            CP_WAIT(1);
        } else {
            CP_WAIT(0);
        }
        __syncthreads();

        const float* xbase = Xsb[k & 1] + (nh + lane) * K1_XROW;
        const float* pbase = Psb[k & 1] + obase * 32;
#pragma unroll
        for (int cq = 0; cq < 8; cq++) {
            ulonglong2 xv[4];
#pragma unroll
            for (int m = 0; m < 4; m++)
                xv[m] = *(const ulonglong2*)(xbase + m * 32 * K1_XROW + cq * 4);
#pragma unroll
            for (int j = 0; j < 8; j++) {
                ulonglong2 pv = *(const ulonglong2*)(pbase + j * 32 + cq * 4);
#pragma unroll
                for (int m = 0; m < 4; m++) {
                    acc[j][m] = fma2(pv.x, xv[m].x, acc[j][m]);
                    acc[j][m] = fma2(pv.y, xv[m].y, acc[j][m]);
                }
            }
        }
    }

#pragma unroll
    for (int j = 0; j < 8; j++) {
        int o = obase + j;
        float* sp = g_S + ((size_t)b * OO + o) * NN + nbase + nh + lane;
#pragma unroll
        for (int m = 0; m < 4; m++) {
            float lo, hi; unpack2(acc[j][m], lo, hi);
            sp[32 * m] = lo + hi + c0s[o];
        }
    }
}

// ---- K2: stats per (b,o): m = max, invl = 1/sum exp(s-m) ----
__global__ __launch_bounds__(256) void k2_stats() {
    int bo = blockIdx.x;             // 512 blocks
    const float4* s4 = (const float4*)(g_S + (size_t)bo * NN);
    int t = threadIdx.x;
    __shared__ float red[256];
    float m = -1e30f;
    for (int q = t; q < NN / 4; q += 256) {
        float4 v = s4[q];
        m = fmaxf(m, fmaxf(fmaxf(v.x, v.y), fmaxf(v.z, v.w)));
    }
    red[t] = m; __syncthreads();
    for (int st = 128; st > 0; st >>= 1) {
        if (t < st) red[t] = fmaxf(red[t], red[t + st]);
        __syncthreads();
    }
    m = red[0]; __syncthreads();
    float sum = 0.f;
    for (int q = t; q < NN / 4; q += 256) {
        float4 v = s4[q];
        sum += __expf(v.x - m) + __expf(v.y - m) + __expf(v.z - m) + __expf(v.w - m);
    }
    red[t] = sum; __syncthreads();
    for (int st = 128; st > 0; st >>= 1) {
        if (t < st) red[t] += red[t + st];
        __syncthreads();
    }
    if (t == 0) { g_m[bo] = m; g_invl[bo] = 1.0f / red[0]; }
}

// ---- K2b: g_Wd[b][n][2o+{0,1}] = exp(S[b][o][n]-m)*invl (transpose + dup) ----
__global__ __launch_bounds__(256) void k2b_transpose() {
    __shared__ float shm[64][33];
    __shared__ float ms[OO], ivs[OO];
    int b = blockIdx.y;
    int nbase = blockIdx.x * 64;
    int t = threadIdx.x;
    if (t < OO) { ms[t] = g_m[b * OO + t]; ivs[t] = g_invl[b * OO + t]; }
#pragma unroll
    for (int r = 0; r < 8; r++) {
        int idx = t + r * 256;           // 0..2047
        int o = idx >> 6, nn = idx & 63;
        shm[nn][o] = g_S[((size_t)b * OO + o) * NN + nbase + nn];
    }
    __syncthreads();
    float* Wb = g_Wd + ((size_t)b * NN + nbase) * (OO * 2);
#pragma unroll
    for (int r = 0; r < 16; r++) {
        int idx = t + r * 256;           // 0..4095
        int nn = idx >> 6, f = idx & 63;
        int o = f >> 1;
        Wb[nn * (OO * 2) + f] = __expf(shm[nn][o] - ms[o]) * ivs[o];
    }
}

// ---- K3: y_part[b,ch,o,c] = sum_n w[b,n,o] * X[b,n,c] ----
// 8 warps: warp w -> o-group (w&3)*8, c-half (w>>2)*256; lane: c = cb + {0..3, 128..131}.
// 32 stages of 16 n, cp.async double-buffered.
#define K3_XBUF (16 * DD)      // 8192 floats
#define K3_WBUF (16 * OO * 2)  // 1024 floats
__global__ __launch_bounds__(256, 2) void k3_accum(const float* __restrict__ X) {
    extern __shared__ float sh[];
    float* Xsb[2] = { sh, sh + K3_XBUF };
    float* Wsb[2] = { sh + 2 * K3_XBUF, sh + 2 * K3_XBUF + K3_WBUF };

    int b = blockIdx.y;
    int ch = blockIdx.x;             // 0..15
    int t = threadIdx.x;
    int w = t >> 5, lane = t & 31;
    int og = (w & 3) * 8;
    int cb = (w >> 2) * 256 + lane * 4;

    const float* Xb = X + ((size_t)b * NN + ch * 512) * DD;
    const float* Wb = g_Wd + ((size_t)b * NN + ch * 512) * (OO * 2);

    auto stage = [&](int s, int buf) {
        float* xd = Xsb[buf];
        float* wd = Wsb[buf];
#pragma unroll
        for (int i = 0; i < 8; i++) {
            int idx = t + i * 256;               // 0..2047
            int n = idx >> 7, ck = idx & 127;
            cp16(xd + n * DD + ck * 4,
                 Xb + (size_t)(s * 16 + n) * DD + ck * 4);
        }
        {
            int n = t >> 4, ck = t & 15;
            cp16(wd + n * (OO * 2) + ck * 4,
                 Wb + (size_t)(s * 16 + n) * (OO * 2) + ck * 4);
        }
    };

    unsigned long long acc[8][4];
#pragma unroll
    for (int j = 0; j < 8; j++)
#pragma unroll
        for (int q = 0; q < 4; q++) acc[j][q] = 0ULL;

    stage(0, 0);
    CP_COMMIT();

#pragma unroll 1
    for (int s = 0; s < 32; s++) {
        __syncthreads();
        if (s + 1 < 32) {
            stage(s + 1, (s + 1) & 1);
            CP_COMMIT();
            CP_WAIT(1);
        } else {
            CP_WAIT(0);
        }
        __syncthreads();

        const float* xs = Xsb[s & 1];
        const float* ws = Wsb[s & 1];
#pragma unroll 2
        for (int n2 = 0; n2 < 16; n2++) {
            const float* wrow = ws + n2 * (OO * 2) + og * 2;
            ulonglong2 w01 = *(const ulonglong2*)(wrow);
            ulonglong2 w23 = *(const ulonglong2*)(wrow + 4);
            ulonglong2 w45 = *(const ulonglong2*)(wrow + 8);
            ulonglong2 w67 = *(const ulonglong2*)(wrow + 12);
            ulonglong2 xa = *(const ulonglong2*)(xs + n2 * DD + cb);
            ulonglong2 xc = *(const ulonglong2*)(xs + n2 * DD + cb + 128);
            acc[0][0] = fma2(w01.x, xa.x, acc[0][0]);
            acc[0][1] = fma2(w01.x, xa.y, acc[0][1]);
            acc[0][2] = fma2(w01.x, xc.x, acc[0][2]);
            acc[0][3] = fma2(w01.x, xc.y, acc[0][3]);
            acc[1][0] = fma2(w01.y, xa.x, acc[1][0]);
            acc[1][1] = fma2(w01.y, xa.y, acc[1][1]);
            acc[1][2] = fma2(w01.y, xc.x, acc[1][2]);
            acc[1][3] = fma2(w01.y, xc.y, acc[1][3]);
            acc[2][0] = fma2(w23.x, xa.x, acc[2][0]);
            acc[2][1] = fma2(w23.x, xa.y, acc[2][1]);
            acc[2][2] = fma2(w23.x, xc.x, acc[2][2]);
            acc[2][3] = fma2(w23.x, xc.y, acc[2][3]);
            acc[3][0] = fma2(w23.y, xa.x, acc[3][0]);
            acc[3][1] = fma2(w23.y, xa.y, acc[3][1]);
            acc[3][2] = fma2(w23.y, xc.x, acc[3][2]);
            acc[3][3] = fma2(w23.y, xc.y, acc[3][3]);
            acc[4][0] = fma2(w45.x, xa.x, acc[4][0]);
            acc[4][1] = fma2(w45.x, xa.y, acc[4][1]);
            acc[4][2] = fma2(w45.x, xc.x, acc[4][2]);
            acc[4][3] = fma2(w45.x, xc.y, acc[4][3]);
            acc[5][0] = fma2(w45.y, xa.x, acc[5][0]);
            acc[5][1] = fma2(w45.y, xa.y, acc[5][1]);
            acc[5][2] = fma2(w45.y, xc.x, acc[5][2]);
            acc[5][3] = fma2(w45.y, xc.y, acc[5][3]);
            acc[6][0] = fma2(w67.x, xa.x, acc[6][0]);
            acc[6][1] = fma2(w67.x, xa.y, acc[6][1]);
            acc[6][2] = fma2(w67.x, xc.x, acc[6][2]);
            acc[6][3] = fma2(w67.x, xc.y, acc[6][3]);
            acc[7][0] = fma2(w67.y, xa.x, acc[7][0]);
            acc[7][1] = fma2(w67.y, xa.y, acc[7][1]);
            acc[7][2] = fma2(w67.y, xc.x, acc[7][2]);
            acc[7][3] = fma2(w67.y, xc.y, acc[7][3]);
        }
    }

    float* yp = g_ypart + (((size_t)b * NCH3 + ch) * OO) * DD;
#pragma unroll
    for (int j = 0; j < 8; j++) {
        float a0, a1, a2, a3, c0_, c1_, c2_, c3_;
        unpack2(acc[j][0], a0, a1);
        unpack2(acc[j][1], a2, a3);
        unpack2(acc[j][2], c0_, c1_);
        unpack2(acc[j][3], c2_, c3_);
        float* base = yp + (size_t)(og + j) * DD + cb;
        *(float4*)(base)       = make_float4(a0, a1, a2, a3);
        *(float4*)(base + 128) = make_float4(c0_, c1_, c2_, c3_);
    }
}

// ---- K4: reduce partials, apply Wv per head, Wo, residual, LayerNorm ----
__global__ __launch_bounds__(256) void k4_final(const float* __restrict__ seed,
                                                const float* __restrict__ Wv,
                                                const float* __restrict__ bv,
                                                const float* __restrict__ Wo,
                                                const float* __restrict__ bo,
                                                const float* __restrict__ gamma,
                                                const float* __restrict__ beta,
                                                float* __restrict__ out) {
    int i = blockIdx.x;  // seed index
    int b = blockIdx.y;
    int t = threadIdx.x; // 256
    __shared__ float ysh[HH * DD];   // 16 KB
    __shared__ float presh[DD];
    __shared__ float red[256];

    for (int idx = t; idx < HH * DD; idx += 256) {
        int h = idx >> 9, c = idx & 511;
        int o = i * HH + h;
        float s = 0.f;
        for (int ch = 0; ch < NCH3; ch++)
            s += g_ypart[(((size_t)b * NCH3 + ch) * OO + o) * DD + c];
        ysh[idx] = s;
    }
    __syncthreads();

    for (int g = t; g < DD; g += 256) {
        int h = g >> 6;
        const float4* wr = (const float4*)(Wv + (size_t)g * DD);
        const float4* yr = (const float4*)(ysh + h * DD);
        float acc = 0.f;
#pragma unroll 4
        for (int c4 = 0; c4 < DD / 4; c4++) {
            float4 w4 = wr[c4], y4 = yr[c4];
            acc += w4.x * y4.x + w4.y * y4.y + w4.z * y4.z + w4.w * y4.w;
        }
        presh[g] = acc + bv[g];
    }
    __syncthreads();

    float zv[2];
#pragma unroll
    for (int gi = 0; gi < 2; gi++) {
        int g = t + gi * 256;
        const float4* wr = (const float4*)(Wo + (size_t)g * DD);
        const float4* pr = (const float4*)presh;
        float acc = 0.f;
#pragma unroll 4
        for (int c4 = 0; c4 < DD / 4; c4++) {
            float4 w4 = wr[c4], p4 = pr[c4];
            acc += w4.x * p4.x + w4.y * p4.y + w4.z * p4.z + w4.w * p4.w;
        }
        zv[gi] = acc + bo[g] + seed[(size_t)i * DD + g];
    }

    red[t] = zv[0] + zv[1]; __syncthreads();
    for (int st = 128; st > 0; st >>= 1) { if (t < st) red[t] += red[t + st]; __syncthreads(); }
    float mu = red[0] * (1.0f / DD); __syncthreads();
    float d0 = zv[0] - mu, d1 = zv[1] - mu;
    red[t] = d0 * d0 + d1 * d1; __syncthreads();
    for (int st = 128; st > 0; st >>= 1) { if (t < st) red[t] += red[t + st]; __syncthreads(); }
    float rstd = rsqrtf(red[0] * (1.0f / DD) + 1e-6f);

    float* op = out + ((size_t)b * KSEED + i) * DD;
#pragma unroll
    for (int gi = 0; gi < 2; gi++) {
        int g = t + gi * 256;
        op[g] = (zv[gi] - mu) * rstd * gamma[g] + beta[g];
    }
}

extern "C" void kernel_launch(void* const* d_in, const int* in_sizes, int n_in,
                              void* d_out, int out_size) {
    const float* X     = (const float*)d_in[0];
    const float* seed  = (const float*)d_in[1];
    const float* Wq    = (const float*)d_in[2];
    const float* bq    = (const float*)d_in[3];
    const float* Wk    = (const float*)d_in[4];
    const float* bk    = (const float*)d_in[5];
    const float* Wv    = (const float*)d_in[6];
    const float* bv    = (const float*)d_in[7];
    const float* Wo    = (const float*)d_in[8];
    const float* bo    = (const float*)d_in[9];
    const float* gamma = (const float*)d_in[10];
    const float* beta  = (const float*)d_in[11];
    float* out = (float*)d_out;

    int k1_smem = (2 * K1_XBUF + 2 * K1_PBUF) * (int)sizeof(float);   // 81920
    int k3_smem = (2 * K3_XBUF + 2 * K3_WBUF) * (int)sizeof(float);   // 73728
    static int configured = 0;
    cudaFuncSetAttribute(k1_scores, cudaFuncAttributeMaxDynamicSharedMemorySize, k1_smem);
    cudaFuncSetAttribute(k3_accum, cudaFuncAttributeMaxDynamicSharedMemorySize, k3_smem);
    (void)configured;

    k0a_q<<<KSEED, DD>>>(seed, Wq, bq);
    k0b_P<<<HH, DD>>>(Wk, bk);
    k1_scores<<<dim3(NN / 256, BB), 256, k1_smem>>>(X);
    k2_stats<<<BB * OO, 256>>>();
    k2b_transpose<<<dim3(NN / 64, BB), 256>>>();
    k3_accum<<<dim3(NCH3, BB), 256, k3_smem>>>(X);
    k4_final<<<dim3(KSEED, BB), 256>>>(seed, Wv, bv, Wo, bo, gamma, beta, out);
}